// round 1
// baseline (speedup 1.0000x reference)
#include <cuda_runtime.h>
#include <math.h>

// Problem constants (fixed by the reference)
#define BN    1024
#define FEATN 512
#define HN    256
#define KC    16      // K-chunk
#define TI    8       // i rows per block tile
#define TJ    8       // j rows per block tile
#define NPAIR 64      // TI*TJ

// h_scores is symmetric: |x_i - x_j| and p_i*p_j are symmetric in (i,j).
// So compute only tiles with jb >= ib and mirror-write.
//
// Block: 256 threads as (tx in [0,16): m-group of 16, ty in [0,16): pair-group of 4)
// Each thread accumulates acc[4 pairs][16 m] over K=512.
// Epilogue: + label rank-2 term + b1, exact GELU, dot W2 (shfl reduce over the
// 16 tx lanes), sigmoid, write hs[i][j] and hs[j][i].

__global__ __launch_bounds__(256, 2)
void scorer_kernel(const float* __restrict__ X,
                   const float* __restrict__ logits,
                   const float* __restrict__ W1,
                   const float* __restrict__ b1,
                   const float* __restrict__ W2,
                   const float* __restrict__ b2,
                   float* __restrict__ hs)
{
    const int ib = blockIdx.y;
    const int jb = blockIdx.x;
    if (jb < ib) return;   // symmetry: upper triangle only

    const int i0 = ib * TI;
    const int j0 = jb * TJ;
    const int tid = threadIdx.x;
    const int tx = tid & 15;
    const int ty = tid >> 4;

    __shared__ float sW1[KC][HN];      // W1 k-chunk  (16 x 256)
    __shared__ float sDiff[KC][NPAIR]; // |xi-xj| tile, f-major
    __shared__ float sXi[TI][KC];
    __shared__ float sXj[TJ][KC];
    __shared__ float sWc0[HN], sWc1[HN], sB1[HN], sW2s[HN];
    __shared__ float sPi[TI][2], sPj[TJ][2];

    // One-time per-block loads
    if (tid < HN) {
        sWc0[tid] = W1[512 * HN + tid];
        sWc1[tid] = W1[513 * HN + tid];
        sB1[tid]  = b1[tid];
        sW2s[tid] = W2[tid];
    }
    if (tid < TI) {
        float l0 = logits[(i0 + tid) * 2 + 0];
        float l1 = logits[(i0 + tid) * 2 + 1];
        float p0 = 1.0f / (1.0f + expf(l1 - l0));
        sPi[tid][0] = p0; sPi[tid][1] = 1.0f - p0;
    } else if (tid < TI + TJ) {
        int r = tid - TI;
        float l0 = logits[(j0 + r) * 2 + 0];
        float l1 = logits[(j0 + r) * 2 + 1];
        float p0 = 1.0f / (1.0f + expf(l1 - l0));
        sPj[r][0] = p0; sPj[r][1] = 1.0f - p0;
    }
    const float b2w = b2[0];

    float acc[4][16];
#pragma unroll
    for (int p = 0; p < 4; p++)
#pragma unroll
        for (int m = 0; m < 16; m++) acc[p][m] = 0.0f;

    for (int k0 = 0; k0 < FEATN; k0 += KC) {
        __syncthreads();  // previous iteration's reads done (also covers 1-time loads)

        // Load W1 chunk: 16 rows x 256 cols = 1024 float4, 4 per thread.
#pragma unroll
        for (int r = 0; r < 4; r++) {
            int lin = tid + 256 * r;          // float4 index 0..1023
            int f  = lin >> 6;                // 0..15
            int m4 = lin & 63;                // 0..63
            *(float4*)&sW1[f][m4 * 4] =
                *(const float4*)&W1[(k0 + f) * HN + m4 * 4];
        }
        // Load X tiles (8 rows x 16 f each)
        if (tid < 128) {
            int r = tid >> 4, f = tid & 15;
            sXi[r][f] = X[(i0 + r) * FEATN + k0 + f];
        } else {
            int t2 = tid - 128;
            int r = t2 >> 4, f = t2 & 15;
            sXj[r][f] = X[(j0 + r) * FEATN + k0 + f];
        }
        __syncthreads();

        // Build |xi - xj| tile: 16 f x 64 pairs, 4 per thread
#pragma unroll
        for (int r = 0; r < 4; r++) {
            int lin = tid + 256 * r;          // 0..1023
            int f  = lin >> 6;
            int pr = lin & 63;
            int pi = pr >> 3, pj = pr & 7;
            sDiff[f][pr] = fabsf(sXi[pi][f] - sXj[pj][f]);
        }
        __syncthreads();

        // Main FMA loop: 16 f x (4 pair x 16 m) outer products
#pragma unroll
        for (int f = 0; f < KC; f++) {
            float af[4];
            *(float4*)&af[0] = *(float4*)&sDiff[f][ty * 4];
            float bf[16];
            *(float4*)&bf[0]  = *(float4*)&sW1[f][tx * 16 + 0];
            *(float4*)&bf[4]  = *(float4*)&sW1[f][tx * 16 + 4];
            *(float4*)&bf[8]  = *(float4*)&sW1[f][tx * 16 + 8];
            *(float4*)&bf[12] = *(float4*)&sW1[f][tx * 16 + 12];
#pragma unroll
            for (int p = 0; p < 4; p++)
#pragma unroll
                for (int m = 0; m < 16; m++)
                    acc[p][m] = fmaf(af[p], bf[m], acc[p][m]);
        }
    }
    __syncthreads();

    // Epilogue: label term + bias, exact GELU, dot W2, sigmoid
#pragma unroll
    for (int p = 0; p < 4; p++) {
        int pr = ty * 4 + p;
        int pi = pr >> 3, pj = pr & 7;
        float c0 = sPi[pi][0] * sPj[pj][0];
        float c1 = sPi[pi][1] * sPj[pj][1];
        float s = 0.0f;
#pragma unroll
        for (int mm = 0; mm < 16; mm++) {
            int m = tx * 16 + mm;
            float x = acc[p][mm] + c0 * sWc0[m] + c1 * sWc1[m] + sB1[m];
            float g = 0.5f * x * (1.0f + erff(x * 0.70710678118654752f));
            s = fmaf(g, sW2s[m], s);
        }
        // reduce over the 16 tx lanes (same ty), xor stays within 16-lane group
#pragma unroll
        for (int off = 8; off > 0; off >>= 1)
            s += __shfl_xor_sync(0xffffffffu, s, off, 16);
        if (tx == 0) {
            float sc = 1.0f / (1.0f + expf(-(s + b2w)));
            hs[(i0 + pi) * BN + (j0 + pj)] = sc;
            hs[(j0 + pj) * BN + (i0 + pi)] = sc;
        }
    }
}

// Row softmax of adj + 5*log(hs + 1e-8). One block per row.
__global__ __launch_bounds__(256)
void softmax_kernel(const float* __restrict__ adj,
                    const float* __restrict__ hs,
                    float* __restrict__ out)
{
    const int row = blockIdx.x;
    const int tid = threadIdx.x;
    __shared__ float red[256];

    float v[4];
    float mx = -3.4e38f;
#pragma unroll
    for (int u = 0; u < 4; u++) {
        int j = tid + 256 * u;
        float s = hs[row * BN + j];
        v[u] = adj[row * BN + j] + 5.0f * logf(s + 1e-8f);
        mx = fmaxf(mx, v[u]);
    }
    red[tid] = mx;
    __syncthreads();
    for (int off = 128; off > 0; off >>= 1) {
        if (tid < off) red[tid] = fmaxf(red[tid], red[tid + off]);
        __syncthreads();
    }
    mx = red[0];
    __syncthreads();

    float sum = 0.0f;
#pragma unroll
    for (int u = 0; u < 4; u++) {
        v[u] = expf(v[u] - mx);
        sum += v[u];
    }
    red[tid] = sum;
    __syncthreads();
    for (int off = 128; off > 0; off >>= 1) {
        if (tid < off) red[tid] += red[tid + off];
        __syncthreads();
    }
    float inv = 1.0f / red[0];
#pragma unroll
    for (int u = 0; u < 4; u++) {
        int j = tid + 256 * u;
        out[row * BN + j] = v[u] * inv;
    }
}

extern "C" void kernel_launch(void* const* d_in, const int* in_sizes, int n_in,
                              void* d_out, int out_size)
{
    const float* X      = (const float*)d_in[0];   // [1024, 512]
    const float* logits = (const float*)d_in[1];   // [1024, 2]
    const float* adj    = (const float*)d_in[2];   // [1024, 1024]
    const float* W1     = (const float*)d_in[3];   // [514, 256]
    const float* b1     = (const float*)d_in[4];   // [256]
    const float* W2     = (const float*)d_in[5];   // [256, 1]
    const float* b2     = (const float*)d_in[6];   // [1]

    float* out = (float*)d_out;          // [adj_refined (1M) | h_scores (1M)]
    float* hs  = out + BN * BN;

    dim3 grid(BN / TJ, BN / TI);         // 128 x 128, lower triangle early-exits
    scorer_kernel<<<grid, 256>>>(X, logits, W1, b1, W2, b2, hs);
    softmax_kernel<<<BN, 256>>>(adj, hs, out);
}

// round 3
// speedup vs baseline: 5.9911x; 5.9911x over previous
#include <cuda_runtime.h>
#include <cuda_bf16.h>
#include <math.h>
#include <stdint.h>

#define BN    1024
#define FEATN 512
#define HN    256
#define TI    8
#define TJ    16
#define MP    128      // pairs per block tile
#define KC    32       // k per chunk
#define NCH   16       // 512/32
#define RS    40       // padded row stride in bf16 elems
#define RSB   80       // ... in bytes (conflict-free for ldmatrix)

// ---- smem layout (bytes from 128B-aligned dynamic base) ----
#define OFF_XI   0               // 8 x 512 f32   = 16384
#define OFF_XJ   16384           // 16 x 512 f32  = 32768
#define OFF_ST   49152           // 2 stages x 61440
#define STAGE_SZ 61440
#define ST_AH    0               // 128 x 80      = 10240
#define ST_AL    10240
#define ST_B     20480           // B_h 20480 then B_l 20480 (contiguous 40960)
#define OFF_EPI  172032          // Wc0,Wc1,b1,W2 : 4 x 256 x 4 = 4096
#define OFF_RED  176128          // 128 x 2 floats
#define SMEM_TOTAL 177152

// Pre-split, pre-transposed, pre-padded W1: [chunk][B_h 1280 | B_l 1280] uint4
__device__ uint4 g_W1s[NCH][2560];

__device__ __forceinline__ uint32_t smem_u32(const void* p) {
    uint32_t a;
    asm("{ .reg .u64 t; cvta.to.shared.u64 t, %1; cvt.u32.u64 %0, t; }" : "=r"(a) : "l"(p));
    return a;
}

#define LDSM_X4(r0,r1,r2,r3,addr) \
    asm volatile("ldmatrix.sync.aligned.m8n8.x4.shared.b16 {%0,%1,%2,%3}, [%4];" \
        : "=r"(r0), "=r"(r1), "=r"(r2), "=r"(r3) : "r"(addr))

#define MMA16816(d, a0,a1,a2,a3, b0,b1) \
    asm volatile("mma.sync.aligned.m16n8k16.row.col.f32.bf16.bf16.f32 " \
        "{%0,%1,%2,%3}, {%4,%5,%6,%7}, {%8,%9}, {%0,%1,%2,%3};" \
        : "+f"((d)[0]), "+f"((d)[1]), "+f"((d)[2]), "+f"((d)[3]) \
        : "r"(a0), "r"(a1), "r"(a2), "r"(a3), "r"(b0), "r"(b1))

#define CP_ASYNC16(dst, src) \
    asm volatile("cp.async.ca.shared.global [%0], [%1], 16;" :: "r"(dst), "l"(src))
#define CP_COMMIT() asm volatile("cp.async.commit_group;" ::: "memory")
#define CP_WAIT0()  asm volatile("cp.async.wait_group 0;" ::: "memory")

// ---------------- prep: W1[0:512] -> bf16 hi/lo, [N,K] padded rows ----------
__global__ void prep_kernel(const float* __restrict__ W1) {
    int k = blockIdx.x;       // 0..511
    int n = threadIdx.x;      // 0..255
    float w = W1[k * HN + n];
    __nv_bfloat16 hi = __float2bfloat16(w);
    float hif = __bfloat162float(hi);
    __nv_bfloat16 lo = __float2bfloat16(w - hif);
    int c = k >> 5, kk = k & 31;
    char* base = (char*)&g_W1s[c][0];
    *(__nv_bfloat16*)(base + n * RSB + kk * 2)         = hi;
    *(__nv_bfloat16*)(base + 20480 + n * RSB + kk * 2) = lo;
}

// ---------------- main scorer ----------------
__device__ __forceinline__ void build_A(const char* SB, uint32_t stg_u32, int c, int tid) {
    int p  = tid >> 2;
    int kq = (tid & 3) * 8;
    const float* xi = (const float*)(SB + OFF_XI) + (p >> 4) * 512 + c * KC + kq;
    const float* xj = (const float*)(SB + OFF_XJ) + (p & 15) * 512 + c * KC + kq;
    float4 xa = *(const float4*)xi,       xb = *(const float4*)(xi + 4);
    float4 ya = *(const float4*)xj,       yb = *(const float4*)(xj + 4);
    float d[8] = { fabsf(xa.x - ya.x), fabsf(xa.y - ya.y), fabsf(xa.z - ya.z), fabsf(xa.w - ya.w),
                   fabsf(xb.x - yb.x), fabsf(xb.y - yb.y), fabsf(xb.z - yb.z), fabsf(xb.w - yb.w) };
    uint32_t h[4], l[4];
#pragma unroll
    for (int u = 0; u < 4; u++) {
        __nv_bfloat162 hb = __float22bfloat162_rn(make_float2(d[2*u], d[2*u+1]));
        float r0 = d[2*u]   - __low2float(hb);
        float r1 = d[2*u+1] - __high2float(hb);
        __nv_bfloat162 lb = __float22bfloat162_rn(make_float2(r0, r1));
        h[u] = *(uint32_t*)&hb;
        l[u] = *(uint32_t*)&lb;
    }
    uint32_t off = (uint32_t)(p * RSB + kq * 2);
    *(uint4*)((char*)SB + (stg_u32 & 0x0fffffffu)) ; // (no-op guard removed below)
    // store via smem pointers (generic) -- stg passed as byte offset instead:
    (void)stg_u32;
    // actual stores done by caller wrapper
    // (kept in one function for clarity)
    char* aH = (char*)SB + ((size_t)(stg_u32)) + ST_AH;
    *(uint4*)(aH + off)          = make_uint4(h[0], h[1], h[2], h[3]);
    *(uint4*)(aH + 10240 + off)  = make_uint4(l[0], l[1], l[2], l[3]);
}

__global__ __launch_bounds__(512, 1)
void scorer_mma(const float* __restrict__ X,
                const float* __restrict__ logits,
                const float* __restrict__ b1,
                const float* __restrict__ W1,
                const float* __restrict__ W2,
                const float* __restrict__ b2,
                float* __restrict__ hs)
{
    const int ib = blockIdx.y;
    const int jb = blockIdx.x;
    if (jb * TJ + (TJ - 1) < ib * TI) return;

    extern __shared__ __align__(128) char SB[];
    const uint32_t sb = smem_u32(SB);

    const int tid  = threadIdx.x;
    const int wid  = tid >> 5;
    const int lane = tid & 31;
    const int i0 = ib * TI, j0 = jb * TJ;

    // ---- preload X rows (fp32) ----
    {
        float4* dXi = (float4*)(SB + OFF_XI);
        float4* dXj = (float4*)(SB + OFF_XJ);
#pragma unroll
        for (int r = 0; r < 2; r++) {
            int idx = tid + 512 * r;              // 1024 float4
            dXi[idx] = ((const float4*)X)[(i0 + (idx >> 7)) * 128 + (idx & 127)];
        }
#pragma unroll
        for (int r = 0; r < 4; r++) {
            int idx = tid + 512 * r;              // 2048 float4
            dXj[idx] = ((const float4*)X)[(j0 + (idx >> 7)) * 128 + (idx & 127)];
        }
        if (tid < 256) {
            float* e = (float*)(SB + OFF_EPI);
            e[tid]       = W1[512 * HN + tid];
            e[256 + tid] = W1[513 * HN + tid];
            e[512 + tid] = b1[tid];
            e[768 + tid] = W2[tid];
        }
    }
    __syncthreads();

    // ---- prologue: chunk 0 into stage 0 ----
    {
        const char* src = (const char*)&g_W1s[0][0];
        uint32_t dst = sb + OFF_ST + ST_B;
#pragma unroll
        for (int r = 0; r < 5; r++) {
            int idx = tid + 512 * r;              // 2560 x 16B
            CP_ASYNC16(dst + idx * 16, src + idx * 16);
        }
        build_A(SB, OFF_ST, 0, tid);
        CP_COMMIT();
    }

    // ---- per-thread ldmatrix offsets ----
    const int m0 = (wid >> 1) * 16;
    const int nc = wid & 1;
    const int n0 = nc * 128;
    const uint32_t aOff = (uint32_t)(((lane & 7) + ((lane >> 3) & 1) * 8 + m0) * RSB
                                     + ((lane >> 4) & 1) * 16);
    const uint32_t bOff = (uint32_t)(((lane & 7) + ((lane >> 4) & 1) * 8) * RSB
                                     + ((lane >> 3) & 1) * 16);

    float d[16][4];
#pragma unroll
    for (int t = 0; t < 16; t++)
#pragma unroll
        for (int r = 0; r < 4; r++) d[t][r] = 0.0f;

    // ---- main K loop ----
    for (int c = 0; c < NCH; c++) {
        const int s = c & 1;
        CP_WAIT0();
        __syncthreads();

        if (c + 1 < NCH) {
            const char* src = (const char*)&g_W1s[c + 1][0];
            uint32_t dst = sb + OFF_ST + (s ^ 1) * STAGE_SZ + ST_B;
#pragma unroll
            for (int r = 0; r < 5; r++) {
                int idx = tid + 512 * r;
                CP_ASYNC16(dst + idx * 16, src + idx * 16);
            }
            build_A(SB, OFF_ST + (s ^ 1) * STAGE_SZ, c + 1, tid);
            CP_COMMIT();
        }

        const uint32_t stg = sb + OFF_ST + s * STAGE_SZ;
#pragma unroll
        for (int ks = 0; ks < 2; ks++) {
            uint32_t ah_addr = stg + ST_AH + aOff + ks * 32;
            uint32_t ahr[4], alr[4];
            LDSM_X4(ahr[0], ahr[1], ahr[2], ahr[3], ah_addr);
            LDSM_X4(alr[0], alr[1], alr[2], alr[3], ah_addr + 10240);
            uint32_t bbase = stg + ST_B + (uint32_t)(n0 * RSB) + bOff + ks * 32;
#pragma unroll
            for (int nt2 = 0; nt2 < 8; nt2++) {
                uint32_t bh_addr = bbase + nt2 * (16 * RSB);
                uint32_t bh[4], bl[4];
                LDSM_X4(bh[0], bh[1], bh[2], bh[3], bh_addr);
                LDSM_X4(bl[0], bl[1], bl[2], bl[3], bh_addr + 20480);
                MMA16816(d[2*nt2],   ahr[0],ahr[1],ahr[2],ahr[3], bh[0], bh[1]);
                MMA16816(d[2*nt2],   ahr[0],ahr[1],ahr[2],ahr[3], bl[0], bl[1]);
                MMA16816(d[2*nt2],   alr[0],alr[1],alr[2],alr[3], bh[0], bh[1]);
                MMA16816(d[2*nt2+1], ahr[0],ahr[1],ahr[2],ahr[3], bh[2], bh[3]);
                MMA16816(d[2*nt2+1], ahr[0],ahr[1],ahr[2],ahr[3], bl[2], bl[3]);
                MMA16816(d[2*nt2+1], alr[0],alr[1],alr[2],alr[3], bh[2], bh[3]);
            }
        }
    }
    __syncthreads();

    // ---- epilogue ----
    const float* eW0 = (const float*)(SB + OFF_EPI);
    const float* eW1 = eW0 + 256;
    const float* eB1 = eW0 + 512;
    const float* eW2 = eW0 + 768;

    const int prow = m0 + (lane >> 2);        // pair row 0
    const int p1   = prow + 8;                // pair row 1
    const int gi0 = i0 + (prow >> 4), gj0 = j0 + (prow & 15);
    const int gi1 = i0 + (p1 >> 4),   gj1 = j0 + (p1 & 15);

    float pia = 1.0f / (1.0f + expf(logits[gi0*2+1] - logits[gi0*2]));
    float pja = 1.0f / (1.0f + expf(logits[gj0*2+1] - logits[gj0*2]));
    float pib = 1.0f / (1.0f + expf(logits[gi1*2+1] - logits[gi1*2]));
    float pjb = 1.0f / (1.0f + expf(logits[gj1*2+1] - logits[gj1*2]));
    float c00 = pia * pja, c10 = (1.0f - pia) * (1.0f - pja);
    float c01 = pib * pjb, c11 = (1.0f - pib) * (1.0f - pjb);

    float s0 = 0.0f, s1 = 0.0f;
#pragma unroll
    for (int nt = 0; nt < 16; nt++) {
        int col = n0 + nt * 8 + (lane & 3) * 2;
#pragma unroll
        for (int e = 0; e < 2; e++) {
            float w0 = eW0[col + e], w1 = eW1[col + e];
            float bb = eB1[col + e], w2 = eW2[col + e];
            float x0 = d[nt][e]     + c00 * w0 + c10 * w1 + bb;
            float x1 = d[nt][2 + e] + c01 * w0 + c11 * w1 + bb;
            float g0 = 0.5f * x0 * (1.0f + erff(x0 * 0.70710678118654752f));
            float g1 = 0.5f * x1 * (1.0f + erff(x1 * 0.70710678118654752f));
            s0 = fmaf(g0, w2, s0);
            s1 = fmaf(g1, w2, s1);
        }
    }
    s0 += __shfl_xor_sync(0xffffffffu, s0, 1);
    s0 += __shfl_xor_sync(0xffffffffu, s0, 2);
    s1 += __shfl_xor_sync(0xffffffffu, s1, 1);
    s1 += __shfl_xor_sync(0xffffffffu, s1, 2);

    float* red = (float*)(SB + OFF_RED);
    if ((lane & 3) == 0) {
        red[prow * 2 + nc] = s0;
        red[p1 * 2 + nc]   = s1;
    }
    __syncthreads();

    if (tid < 128) {
        int p = tid;
        float tot = red[p * 2] + red[p * 2 + 1] + b2[0];
        float sc = 1.0f / (1.0f + expf(-tot));
        int gi = i0 + (p >> 4), gj = j0 + (p & 15);
        hs[gi * BN + gj] = sc;
        hs[gj * BN + gi] = sc;
    }
}

// ---------------- row softmax of adj + 5*log(hs + 1e-8) ----------------
__global__ __launch_bounds__(256)
void softmax_kernel(const float* __restrict__ adj,
                    const float* __restrict__ hs,
                    float* __restrict__ out)
{
    const int row = blockIdx.x;
    const int tid = threadIdx.x;
    __shared__ float red[256];

    float v[4];
    float mx = -3.4e38f;
#pragma unroll
    for (int u = 0; u < 4; u++) {
        int j = tid + 256 * u;
        float s = hs[row * BN + j];
        v[u] = adj[row * BN + j] + 5.0f * logf(s + 1e-8f);
        mx = fmaxf(mx, v[u]);
    }
    red[tid] = mx;
    __syncthreads();
    for (int off = 128; off > 0; off >>= 1) {
        if (tid < off) red[tid] = fmaxf(red[tid], red[tid + off]);
        __syncthreads();
    }
    mx = red[0];
    __syncthreads();

    float sum = 0.0f;
#pragma unroll
    for (int u = 0; u < 4; u++) {
        v[u] = expf(v[u] - mx);
        sum += v[u];
    }
    red[tid] = sum;
    __syncthreads();
    for (int off = 128; off > 0; off >>= 1) {
        if (tid < off) red[tid] += red[tid + off];
        __syncthreads();
    }
    float inv = 1.0f / red[0];
#pragma unroll
    for (int u = 0; u < 4; u++) {
        int j = tid + 256 * u;
        out[row * BN + j] = v[u] * inv;
    }
}

extern "C" void kernel_launch(void* const* d_in, const int* in_sizes, int n_in,
                              void* d_out, int out_size)
{
    const float* X      = (const float*)d_in[0];   // [1024, 512]
    const float* logits = (const float*)d_in[1];   // [1024, 2]
    const float* adj    = (const float*)d_in[2];   // [1024, 1024]
    const float* W1     = (const float*)d_in[3];   // [514, 256]
    const float* b1     = (const float*)d_in[4];   // [256]
    const float* W2     = (const float*)d_in[5];   // [256, 1]
    const float* b2     = (const float*)d_in[6];   // [1]

    float* out = (float*)d_out;          // [adj_refined (1M) | h_scores (1M)]
    float* hs  = out + BN * BN;

    static int configured = 0;
    if (!configured) {
        cudaFuncSetAttribute(scorer_mma, cudaFuncAttributeMaxDynamicSharedMemorySize, SMEM_TOTAL);
        configured = 1;
    }

    prep_kernel<<<FEATN, HN>>>(W1);
    dim3 grid(BN / TJ, BN / TI);   // (64, 128)
    scorer_mma<<<grid, 512, SMEM_TOTAL>>>(X, logits, b1, W1, W2, b2, hs);
    softmax_kernel<<<BN, 256>>>(adj, hs, out);
}

// round 4
// speedup vs baseline: 6.6749x; 1.1141x over previous
#include <cuda_runtime.h>
#include <cuda_bf16.h>
#include <math.h>
#include <stdint.h>

#define BN    1024
#define FEATN 512
#define HN    256
#define TI    8
#define TJ    16
#define KC    32       // k per chunk
#define NCH   16       // 512/32
#define RSB   80       // padded row stride in bytes (conflict-free ldmatrix)

// ---- smem layout (bytes from 128B-aligned dynamic base) ----
#define OFF_XI   0               // 8 x 512 f32   = 16384
#define OFF_XJ   16384           // 16 x 512 f32  = 32768
#define OFF_ST   49152           // 2 stages x 61440
#define STAGE_SZ 61440
#define ST_AH    0               // A_h 128x80 = 10240 ; A_l at +10240
#define ST_B     20480           // B_h 20480 | B_l 20480
#define OFF_EPI  172032          // float4 per col: 256 x 16 = 4096
#define OFF_RED  176128          // 128 x 4 floats = 2048
#define SMEM_TOTAL 178176

// Pre-split, pre-transposed, pre-padded W1: [chunk][B_h 1280 | B_l 1280] uint4
__device__ uint4 g_W1s[NCH][2560];

__device__ __forceinline__ uint32_t smem_u32(const void* p) {
    uint32_t a;
    asm("{ .reg .u64 t; cvta.to.shared.u64 t, %1; cvt.u32.u64 %0, t; }" : "=r"(a) : "l"(p));
    return a;
}

#define LDSM_X4(r0,r1,r2,r3,addr) \
    asm volatile("ldmatrix.sync.aligned.m8n8.x4.shared.b16 {%0,%1,%2,%3}, [%4];" \
        : "=r"(r0), "=r"(r1), "=r"(r2), "=r"(r3) : "r"(addr))

#define MMA16816(d, a0,a1,a2,a3, b0,b1) \
    asm volatile("mma.sync.aligned.m16n8k16.row.col.f32.bf16.bf16.f32 " \
        "{%0,%1,%2,%3}, {%4,%5,%6,%7}, {%8,%9}, {%0,%1,%2,%3};" \
        : "+f"((d)[0]), "+f"((d)[1]), "+f"((d)[2]), "+f"((d)[3]) \
        : "r"(a0), "r"(a1), "r"(a2), "r"(a3), "r"(b0), "r"(b1))

#define CP_ASYNC16(dst, src) \
    asm volatile("cp.async.cg.shared.global [%0], [%1], 16;" :: "r"(dst), "l"(src))
#define CP_COMMIT() asm volatile("cp.async.commit_group;" ::: "memory")
#define CP_WAIT0()  asm volatile("cp.async.wait_group 0;" ::: "memory")

// branch-free exact-enough GELU: erf via A&S 7.1.26 (abs err < 1.5e-7)
__device__ __forceinline__ float gelu_erf(float x) {
    float u = 0.70710678118654752f * x;
    float a = fabsf(u);
    float den = fmaf(0.3275911f, a, 1.0f);
    float t;
    asm("rcp.approx.f32 %0, %1;" : "=f"(t) : "f"(den));
    float p = fmaf(fmaf(fmaf(fmaf(1.061405429f, t, -1.453152027f), t,
                             1.421413741f), t, -0.284496736f), t, 0.254829592f) * t;
    float e;
    asm("ex2.approx.f32 %0, %1;" : "=f"(e) : "f"(-a * a * 1.4426950408889634f));
    float erfa = fmaf(-p, e, 1.0f);
    float erfu = copysignf(erfa, u);
    return 0.5f * x * (1.0f + erfu);
}

// ---------------- prep: W1[0:512] -> bf16 hi/lo, [N,K] padded rows ----------
__global__ void prep_kernel(const float* __restrict__ W1) {
    int k = blockIdx.x;       // 0..511
    int n = threadIdx.x;      // 0..255
    float w = W1[k * HN + n];
    __nv_bfloat16 hi = __float2bfloat16(w);
    float hif = __bfloat162float(hi);
    __nv_bfloat16 lo = __float2bfloat16(w - hif);
    int c = k >> 5, kk = k & 31;
    char* base = (char*)&g_W1s[c][0];
    *(__nv_bfloat16*)(base + n * RSB + kk * 2)         = hi;
    *(__nv_bfloat16*)(base + 20480 + n * RSB + kk * 2) = lo;
}

// ---------------- A build: |xi - xj| split bf16 hi/lo into stage ------------
__device__ __forceinline__ void build_A(char* SB, uint32_t stg_off, int c, int tid) {
    int p  = tid >> 2;
    int kq = (tid & 3) * 8;
    const float* xi = (const float*)(SB + OFF_XI) + (p >> 4) * 512 + c * KC + kq;
    const float* xj = (const float*)(SB + OFF_XJ) + (p & 15) * 512 + c * KC + kq;
    float4 xa = *(const float4*)xi, xb = *(const float4*)(xi + 4);
    float4 ya = *(const float4*)xj, yb = *(const float4*)(xj + 4);
    float d[8] = { fabsf(xa.x - ya.x), fabsf(xa.y - ya.y), fabsf(xa.z - ya.z), fabsf(xa.w - ya.w),
                   fabsf(xb.x - yb.x), fabsf(xb.y - yb.y), fabsf(xb.z - yb.z), fabsf(xb.w - yb.w) };
    uint32_t h[4], l[4];
#pragma unroll
    for (int u = 0; u < 4; u++) {
        __nv_bfloat162 hb = __float22bfloat162_rn(make_float2(d[2*u], d[2*u+1]));
        float r0 = d[2*u]   - __low2float(hb);
        float r1 = d[2*u+1] - __high2float(hb);
        __nv_bfloat162 lb = __float22bfloat162_rn(make_float2(r0, r1));
        h[u] = *(uint32_t*)&hb;
        l[u] = *(uint32_t*)&lb;
    }
    uint32_t off = (uint32_t)(p * RSB + kq * 2);
    char* aH = SB + stg_off + ST_AH;
    *(uint4*)(aH + off)         = make_uint4(h[0], h[1], h[2], h[3]);
    *(uint4*)(aH + 10240 + off) = make_uint4(l[0], l[1], l[2], l[3]);
}

// ---------------- main scorer ----------------
__global__ __launch_bounds__(512, 1)
void scorer_mma(const float* __restrict__ X,
                const float* __restrict__ logits,
                const float* __restrict__ b1,
                const float* __restrict__ W1,
                const float* __restrict__ W2,
                const float* __restrict__ b2,
                float* __restrict__ hs)
{
    const int ib = blockIdx.y;
    const int jb = blockIdx.x;
    if (jb * TJ + (TJ - 1) < ib * TI) return;

    extern __shared__ __align__(128) char SB[];
    const uint32_t sb = smem_u32(SB);

    const int tid  = threadIdx.x;
    const int wid  = tid >> 5;
    const int lane = tid & 31;
    const int i0 = ib * TI, j0 = jb * TJ;

    // warp tiling: 4 M-groups x 4 N-groups; warp covers M32 x N64
    const int mg = wid >> 2, ng = wid & 3;
    const int m0 = mg * 32, n0 = ng * 64;

    // ---- preload X rows (fp32) + epilogue constants ----
    {
        float4* dXi = (float4*)(SB + OFF_XI);
        float4* dXj = (float4*)(SB + OFF_XJ);
#pragma unroll
        for (int r = 0; r < 2; r++) {
            int idx = tid + 512 * r;              // 1024 float4
            dXi[idx] = ((const float4*)X)[(i0 + (idx >> 7)) * 128 + (idx & 127)];
        }
#pragma unroll
        for (int r = 0; r < 4; r++) {
            int idx = tid + 512 * r;              // 2048 float4
            dXj[idx] = ((const float4*)X)[(j0 + (idx >> 7)) * 128 + (idx & 127)];
        }
        if (tid < 256) {
            float4* e = (float4*)(SB + OFF_EPI);
            e[tid] = make_float4(W1[512 * HN + tid], W1[513 * HN + tid],
                                 b1[tid], W2[tid]);
        }
    }
    __syncthreads();

    // ---- prologue: chunk 0 into stage 0 ----
    {
        const char* src = (const char*)&g_W1s[0][0];
        uint32_t dst = sb + OFF_ST + ST_B;
#pragma unroll
        for (int r = 0; r < 5; r++) {
            int idx = tid + 512 * r;              // 2560 x 16B
            CP_ASYNC16(dst + idx * 16, src + idx * 16);
        }
        build_A(SB, OFF_ST, 0, tid);
        CP_COMMIT();
    }

    // ---- per-thread ldmatrix base offsets ----
    const uint32_t aBase = (uint32_t)((m0 + (lane & 7) + ((lane >> 3) & 1) * 8) * RSB
                                      + ((lane >> 4) & 1) * 16);
    const uint32_t bBase = (uint32_t)((n0 + (lane & 7) + ((lane >> 4) & 1) * 8) * RSB
                                      + ((lane >> 3) & 1) * 16);

    float d[2][4][2][4];
#pragma unroll
    for (int a = 0; a < 2; a++)
#pragma unroll
        for (int b = 0; b < 4; b++)
#pragma unroll
            for (int cc = 0; cc < 2; cc++)
#pragma unroll
                for (int r = 0; r < 4; r++) d[a][b][cc][r] = 0.0f;

    // ---- main K loop ----
    for (int c = 0; c < NCH; c++) {
        const int s = c & 1;
        CP_WAIT0();
        __syncthreads();

        if (c + 1 < NCH) {
            const char* src = (const char*)&g_W1s[c + 1][0];
            uint32_t dst = sb + OFF_ST + (s ^ 1) * STAGE_SZ + ST_B;
#pragma unroll
            for (int r = 0; r < 5; r++) {
                int idx = tid + 512 * r;
                CP_ASYNC16(dst + idx * 16, src + idx * 16);
            }
            build_A(SB, OFF_ST + (s ^ 1) * STAGE_SZ, c + 1, tid);
            CP_COMMIT();
        }

        const uint32_t stg = sb + OFF_ST + s * STAGE_SZ;
#pragma unroll
        for (int ks = 0; ks < 2; ks++) {
            uint32_t ahr[2][4], alr[2][4];
#pragma unroll
            for (int m2 = 0; m2 < 2; m2++) {
                uint32_t aa = stg + ST_AH + aBase + m2 * (16 * RSB) + ks * 32;
                LDSM_X4(ahr[m2][0], ahr[m2][1], ahr[m2][2], ahr[m2][3], aa);
                LDSM_X4(alr[m2][0], alr[m2][1], alr[m2][2], alr[m2][3], aa + 10240);
            }
#pragma unroll
            for (int nt = 0; nt < 4; nt++) {
                uint32_t ba = stg + ST_B + bBase + nt * (16 * RSB) + ks * 32;
                uint32_t bh[4], bl[4];
                LDSM_X4(bh[0], bh[1], bh[2], bh[3], ba);
                LDSM_X4(bl[0], bl[1], bl[2], bl[3], ba + 20480);
#pragma unroll
                for (int m2 = 0; m2 < 2; m2++) {
                    MMA16816(d[m2][nt][0], ahr[m2][0],ahr[m2][1],ahr[m2][2],ahr[m2][3], bh[0], bh[1]);
                    MMA16816(d[m2][nt][0], ahr[m2][0],ahr[m2][1],ahr[m2][2],ahr[m2][3], bl[0], bl[1]);
                    MMA16816(d[m2][nt][0], alr[m2][0],alr[m2][1],alr[m2][2],alr[m2][3], bh[0], bh[1]);
                    MMA16816(d[m2][nt][1], ahr[m2][0],ahr[m2][1],ahr[m2][2],ahr[m2][3], bh[2], bh[3]);
                    MMA16816(d[m2][nt][1], ahr[m2][0],ahr[m2][1],ahr[m2][2],ahr[m2][3], bl[2], bl[3]);
                    MMA16816(d[m2][nt][1], alr[m2][0],alr[m2][1],alr[m2][2],alr[m2][3], bh[2], bh[3]);
                }
            }
        }
    }
    __syncthreads();

    // ---- epilogue ----
    // rows handled by this thread: p = m0 + (lane>>2) + 8*rr, rr=0..3
    float c0[4], c1[4], sacc[4];
#pragma unroll
    for (int rr = 0; rr < 4; rr++) {
        int p = m0 + (lane >> 2) + 8 * rr;
        int gi = i0 + (p >> 4), gj = j0 + (p & 15);
        float pi = 1.0f / (1.0f + expf(logits[gi*2+1] - logits[gi*2]));
        float pj = 1.0f / (1.0f + expf(logits[gj*2+1] - logits[gj*2]));
        c0[rr] = pi * pj;
        c1[rr] = (1.0f - pi) * (1.0f - pj);
        sacc[rr] = 0.0f;
    }

    const float4* epi4 = (const float4*)(SB + OFF_EPI);
#pragma unroll
    for (int nt = 0; nt < 4; nt++)
#pragma unroll
        for (int half = 0; half < 2; half++)
#pragma unroll
            for (int e = 0; e < 2; e++) {
                int col = n0 + nt * 16 + half * 8 + (lane & 3) * 2 + e;
                float4 w = epi4[col];
#pragma unroll
                for (int rr = 0; rr < 4; rr++) {
                    int m2 = rr >> 1;
                    int idx = (rr & 1) * 2 + e;
                    float x = d[m2][nt][half][idx]
                            + c0[rr] * w.x + c1[rr] * w.y + w.z;
                    sacc[rr] = fmaf(gelu_erf(x), w.w, sacc[rr]);
                }
            }

#pragma unroll
    for (int rr = 0; rr < 4; rr++) {
        sacc[rr] += __shfl_xor_sync(0xffffffffu, sacc[rr], 1);
        sacc[rr] += __shfl_xor_sync(0xffffffffu, sacc[rr], 2);
    }
    float* red = (float*)(SB + OFF_RED);
    if ((lane & 3) == 0) {
#pragma unroll
        for (int rr = 0; rr < 4; rr++) {
            int p = m0 + (lane >> 2) + 8 * rr;
            red[p * 4 + ng] = sacc[rr];
        }
    }
    __syncthreads();

    if (tid < 128) {
        int p = tid;
        float4 r4 = *(const float4*)&red[p * 4];
        float tot = (r4.x + r4.y) + (r4.z + r4.w) + b2[0];
        float sc = 1.0f / (1.0f + expf(-tot));
        int gi = i0 + (p >> 4), gj = j0 + (p & 15);
        hs[gi * BN + gj] = sc;
        hs[gj * BN + gi] = sc;
    }
}

// ---------------- row softmax of adj + 5*log(hs + 1e-8) ----------------
__global__ __launch_bounds__(256)
void softmax_kernel(const float* __restrict__ adj,
                    const float* __restrict__ hs,
                    float* __restrict__ out)
{
    const int row = blockIdx.x;
    const int tid = threadIdx.x;
    __shared__ float red[256];

    float v[4];
    float mx = -3.4e38f;
#pragma unroll
    for (int u = 0; u < 4; u++) {
        int j = tid + 256 * u;
        float s = hs[row * BN + j];
        v[u] = adj[row * BN + j] + 5.0f * logf(s + 1e-8f);
        mx = fmaxf(mx, v[u]);
    }
    red[tid] = mx;
    __syncthreads();
    for (int off = 128; off > 0; off >>= 1) {
        if (tid < off) red[tid] = fmaxf(red[tid], red[tid + off]);
        __syncthreads();
    }
    mx = red[0];
    __syncthreads();

    float sum = 0.0f;
#pragma unroll
    for (int u = 0; u < 4; u++) {
        v[u] = expf(v[u] - mx);
        sum += v[u];
    }
    red[tid] = sum;
    __syncthreads();
    for (int off = 128; off > 0; off >>= 1) {
        if (tid < off) red[tid] += red[tid + off];
        __syncthreads();
    }
    float inv = 1.0f / red[0];
#pragma unroll
    for (int u = 0; u < 4; u++) {
        int j = tid + 256 * u;
        out[row * BN + j] = v[u] * inv;
    }
}

extern "C" void kernel_launch(void* const* d_in, const int* in_sizes, int n_in,
                              void* d_out, int out_size)
{
    const float* X      = (const float*)d_in[0];   // [1024, 512]
    const float* logits = (const float*)d_in[1];   // [1024, 2]
    const float* adj    = (const float*)d_in[2];   // [1024, 1024]
    const float* W1     = (const float*)d_in[3];   // [514, 256]
    const float* b1     = (const float*)d_in[4];   // [256]
    const float* W2     = (const float*)d_in[5];   // [256, 1]
    const float* b2     = (const float*)d_in[6];   // [1]

    float* out = (float*)d_out;          // [adj_refined (1M) | h_scores (1M)]
    float* hs  = out + BN * BN;

    static int configured = 0;
    if (!configured) {
        cudaFuncSetAttribute(scorer_mma, cudaFuncAttributeMaxDynamicSharedMemorySize, SMEM_TOTAL);
        configured = 1;
    }

    prep_kernel<<<FEATN, HN>>>(W1);
    dim3 grid(BN / TJ, BN / TI);   // (64, 128)
    scorer_mma<<<grid, 512, SMEM_TOTAL>>>(X, logits, b1, W1, W2, b2, hs);
    softmax_kernel<<<BN, 256>>>(adj, hs, out);
}

// round 5
// speedup vs baseline: 7.1278x; 1.0678x over previous
#include <cuda_runtime.h>
#include <cuda_bf16.h>
#include <math.h>
#include <stdint.h>

#define BN    1024
#define FEATN 512
#define HN    256
#define TI    4
#define TJ    16
#define KC    16       // k per chunk
#define NCH   32       // 512/16
#define RSB   48       // padded row stride bytes: (12r)%32 banks -> conflict-free

// ---- smem layout (bytes from 128B-aligned dynamic base) ----
#define OFF_XI   0               // 4 x 512 f32  = 8192
#define OFF_XJ   8192            // 16 x 512 f32 = 32768
#define OFF_ST   40960           // 2 stages x 30720
#define STAGE_SZ 30720
#define ST_AH    0               // A_h 64x48 = 3072 ; A_l at +3072
#define ST_B     6144            // B_h 12288 | B_l 12288
#define OFF_EPI  102400          // float4 per col: 256 x 16 = 4096
#define OFF_RED  106496          // 64 x 4 floats = 1024
#define SMEM_TOTAL 107520

// Pre-split, pre-transposed, pre-padded W1: [chunk][B_h 768 | B_l 768] uint4
__device__ uint4 g_W1s[NCH][1536];

__device__ __forceinline__ uint32_t smem_u32(const void* p) {
    uint32_t a;
    asm("{ .reg .u64 t; cvta.to.shared.u64 t, %1; cvt.u32.u64 %0, t; }" : "=r"(a) : "l"(p));
    return a;
}

#define LDSM_X4(r0,r1,r2,r3,addr) \
    asm volatile("ldmatrix.sync.aligned.m8n8.x4.shared.b16 {%0,%1,%2,%3}, [%4];" \
        : "=r"(r0), "=r"(r1), "=r"(r2), "=r"(r3) : "r"(addr))

#define MMA16816(d, a0,a1,a2,a3, b0,b1) \
    asm volatile("mma.sync.aligned.m16n8k16.row.col.f32.bf16.bf16.f32 " \
        "{%0,%1,%2,%3}, {%4,%5,%6,%7}, {%8,%9}, {%0,%1,%2,%3};" \
        : "+f"((d)[0]), "+f"((d)[1]), "+f"((d)[2]), "+f"((d)[3]) \
        : "r"(a0), "r"(a1), "r"(a2), "r"(a3), "r"(b0), "r"(b1))

#define CP_ASYNC16(dst, src) \
    asm volatile("cp.async.cg.shared.global [%0], [%1], 16;" :: "r"(dst), "l"(src))
#define CP_COMMIT() asm volatile("cp.async.commit_group;" ::: "memory")
#define CP_WAIT0()  asm volatile("cp.async.wait_group 0;" ::: "memory")

// branch-free GELU: erf via A&S 7.1.26 (abs err < 1.5e-7)
__device__ __forceinline__ float gelu_erf(float x) {
    float u = 0.70710678118654752f * x;
    float a = fabsf(u);
    float den = fmaf(0.3275911f, a, 1.0f);
    float t;
    asm("rcp.approx.f32 %0, %1;" : "=f"(t) : "f"(den));
    float p = fmaf(fmaf(fmaf(fmaf(1.061405429f, t, -1.453152027f), t,
                             1.421413741f), t, -0.284496736f), t, 0.254829592f) * t;
    float e;
    asm("ex2.approx.f32 %0, %1;" : "=f"(e) : "f"(-a * a * 1.4426950408889634f));
    float erfa = fmaf(-p, e, 1.0f);
    float erfu = copysignf(erfa, u);
    return 0.5f * x * (1.0f + erfu);
}

// ---------------- prep: W1[0:512] -> bf16 hi/lo, [N,K] 48B-padded rows -------
__global__ void prep_kernel(const float* __restrict__ W1) {
    int k = blockIdx.x;       // 0..511
    int n = threadIdx.x;      // 0..255
    float w = W1[k * HN + n];
    __nv_bfloat16 hi = __float2bfloat16(w);
    float hif = __bfloat162float(hi);
    __nv_bfloat16 lo = __float2bfloat16(w - hif);
    int c = k >> 4, kk = k & 15;
    char* base = (char*)&g_W1s[c][0];
    *(__nv_bfloat16*)(base + n * RSB + kk * 2)         = hi;
    *(__nv_bfloat16*)(base + 12288 + n * RSB + kk * 2) = lo;
}

// ---------------- A build: |xi - xj| split bf16 hi/lo into stage ------------
__device__ __forceinline__ void build_A(char* SB, uint32_t stg_off, int c, int tid) {
    int p  = tid >> 2;            // pair 0..63
    int k4 = (tid & 3) * 4;       // k offset 0,4,8,12
    const float* xi = (const float*)(SB + OFF_XI) + (p >> 4) * 512 + c * KC + k4;
    const float* xj = (const float*)(SB + OFF_XJ) + (p & 15) * 512 + c * KC + k4;
    float4 xa = *(const float4*)xi;
    float4 ya = *(const float4*)xj;
    float d0 = fabsf(xa.x - ya.x), d1 = fabsf(xa.y - ya.y);
    float d2 = fabsf(xa.z - ya.z), d3 = fabsf(xa.w - ya.w);
    __nv_bfloat162 h01 = __float22bfloat162_rn(make_float2(d0, d1));
    __nv_bfloat162 h23 = __float22bfloat162_rn(make_float2(d2, d3));
    __nv_bfloat162 l01 = __float22bfloat162_rn(make_float2(d0 - __low2float(h01), d1 - __high2float(h01)));
    __nv_bfloat162 l23 = __float22bfloat162_rn(make_float2(d2 - __low2float(h23), d3 - __high2float(h23)));
    uint32_t off = (uint32_t)(p * RSB + k4 * 2);
    char* aH = SB + stg_off + ST_AH;
    *(uint2*)(aH + off)        = make_uint2(*(uint32_t*)&h01, *(uint32_t*)&h23);
    *(uint2*)(aH + 3072 + off) = make_uint2(*(uint32_t*)&l01, *(uint32_t*)&l23);
}

// ---------------- main scorer: 256 thr, tile M64 x N256, 2 CTAs/SM ----------
__global__ __launch_bounds__(256, 2)
void scorer_mma(const float* __restrict__ X,
                const float* __restrict__ logits,
                const float* __restrict__ b1,
                const float* __restrict__ W1,
                const float* __restrict__ W2,
                const float* __restrict__ b2,
                float* __restrict__ hs)
{
    const int ib = blockIdx.y;           // 0..255 (TI=4)
    const int jb = blockIdx.x;           // 0..63  (TJ=16)
    if (jb * TJ + (TJ - 1) < ib * TI) return;

    extern __shared__ __align__(128) char SB[];
    const uint32_t sb = smem_u32(SB);

    const int tid  = threadIdx.x;
    const int wid  = tid >> 5;
    const int lane = tid & 31;
    const int i0 = ib * TI, j0 = jb * TJ;

    // 8 warps: 2 M-groups x 4 N-groups; warp covers M32 x N64
    const int mg = wid >> 2, ng = wid & 3;
    const int m0 = mg * 32, n0 = ng * 64;

    // ---- preload X rows (fp32) + epilogue constants ----
    {
        float4* dXi = (float4*)(SB + OFF_XI);
        float4* dXj = (float4*)(SB + OFF_XJ);
#pragma unroll
        for (int r = 0; r < 2; r++) {
            int idx = tid + 256 * r;              // 512 float4
            dXi[idx] = ((const float4*)X)[(i0 + (idx >> 7)) * 128 + (idx & 127)];
        }
#pragma unroll
        for (int r = 0; r < 8; r++) {
            int idx = tid + 256 * r;              // 2048 float4
            dXj[idx] = ((const float4*)X)[(j0 + (idx >> 7)) * 128 + (idx & 127)];
        }
        float4* e = (float4*)(SB + OFF_EPI);
        e[tid] = make_float4(W1[512 * HN + tid], W1[513 * HN + tid],
                             b1[tid], W2[tid]);
    }
    __syncthreads();

    // ---- prologue: chunk 0 into stage 0 ----
    {
        const char* src = (const char*)&g_W1s[0][0];
        uint32_t dst = sb + OFF_ST + ST_B;
#pragma unroll
        for (int r = 0; r < 6; r++) {
            int idx = tid + 256 * r;              // 1536 x 16B
            CP_ASYNC16(dst + idx * 16, src + idx * 16);
        }
        build_A(SB, OFF_ST, 0, tid);
        CP_COMMIT();
    }

    // ---- per-thread ldmatrix base offsets ----
    const uint32_t aBase = (uint32_t)((m0 + (lane & 7) + ((lane >> 3) & 1) * 8) * RSB
                                      + ((lane >> 4) & 1) * 16);
    const uint32_t bBase = (uint32_t)((n0 + (lane & 7) + ((lane >> 4) & 1) * 8) * RSB
                                      + ((lane >> 3) & 1) * 16);

    float d[2][4][2][4];
#pragma unroll
    for (int a = 0; a < 2; a++)
#pragma unroll
        for (int b = 0; b < 4; b++)
#pragma unroll
            for (int cc = 0; cc < 2; cc++)
#pragma unroll
                for (int r = 0; r < 4; r++) d[a][b][cc][r] = 0.0f;

    // ---- main K loop ----
    for (int c = 0; c < NCH; c++) {
        const int s = c & 1;
        CP_WAIT0();
        __syncthreads();

        if (c + 1 < NCH) {
            const char* src = (const char*)&g_W1s[c + 1][0];
            uint32_t dst = sb + OFF_ST + (s ^ 1) * STAGE_SZ + ST_B;
#pragma unroll
            for (int r = 0; r < 6; r++) {
                int idx = tid + 256 * r;
                CP_ASYNC16(dst + idx * 16, src + idx * 16);
            }
            build_A(SB, OFF_ST + (s ^ 1) * STAGE_SZ, c + 1, tid);
            CP_COMMIT();
        }

        const uint32_t stg = sb + OFF_ST + s * STAGE_SZ;
        uint32_t ahr[2][4], alr[2][4];
#pragma unroll
        for (int m2 = 0; m2 < 2; m2++) {
            uint32_t aa = stg + ST_AH + aBase + m2 * (16 * RSB);
            LDSM_X4(ahr[m2][0], ahr[m2][1], ahr[m2][2], ahr[m2][3], aa);
            LDSM_X4(alr[m2][0], alr[m2][1], alr[m2][2], alr[m2][3], aa + 3072);
        }
#pragma unroll
        for (int nt = 0; nt < 4; nt++) {
            uint32_t ba = stg + ST_B + bBase + nt * (16 * RSB);
            uint32_t bh[4], bl[4];
            LDSM_X4(bh[0], bh[1], bh[2], bh[3], ba);
            LDSM_X4(bl[0], bl[1], bl[2], bl[3], ba + 12288);
#pragma unroll
            for (int m2 = 0; m2 < 2; m2++) {
                MMA16816(d[m2][nt][0], ahr[m2][0],ahr[m2][1],ahr[m2][2],ahr[m2][3], bh[0], bh[1]);
                MMA16816(d[m2][nt][0], ahr[m2][0],ahr[m2][1],ahr[m2][2],ahr[m2][3], bl[0], bl[1]);
                MMA16816(d[m2][nt][0], alr[m2][0],alr[m2][1],alr[m2][2],alr[m2][3], bh[0], bh[1]);
                MMA16816(d[m2][nt][1], ahr[m2][0],ahr[m2][1],ahr[m2][2],ahr[m2][3], bh[2], bh[3]);
                MMA16816(d[m2][nt][1], ahr[m2][0],ahr[m2][1],ahr[m2][2],ahr[m2][3], bl[2], bl[3]);
                MMA16816(d[m2][nt][1], alr[m2][0],alr[m2][1],alr[m2][2],alr[m2][3], bh[2], bh[3]);
            }
        }
    }
    __syncthreads();

    // ---- epilogue ----
    float c0[4], c1[4], sacc[4];
#pragma unroll
    for (int rr = 0; rr < 4; rr++) {
        int p = m0 + (lane >> 2) + 8 * rr;
        int gi = i0 + (p >> 4), gj = j0 + (p & 15);
        float pi = 1.0f / (1.0f + expf(logits[gi*2+1] - logits[gi*2]));
        float pj = 1.0f / (1.0f + expf(logits[gj*2+1] - logits[gj*2]));
        c0[rr] = pi * pj;
        c1[rr] = (1.0f - pi) * (1.0f - pj);
        sacc[rr] = 0.0f;
    }

    const float4* epi4 = (const float4*)(SB + OFF_EPI);
#pragma unroll
    for (int nt = 0; nt < 4; nt++)
#pragma unroll
        for (int half = 0; half < 2; half++)
#pragma unroll
            for (int e = 0; e < 2; e++) {
                int col = n0 + nt * 16 + half * 8 + (lane & 3) * 2 + e;
                float4 w = epi4[col];
#pragma unroll
                for (int rr = 0; rr < 4; rr++) {
                    int m2 = rr >> 1;
                    int idx = (rr & 1) * 2 + e;
                    float x = d[m2][nt][half][idx]
                            + c0[rr] * w.x + c1[rr] * w.y + w.z;
                    sacc[rr] = fmaf(gelu_erf(x), w.w, sacc[rr]);
                }
            }

#pragma unroll
    for (int rr = 0; rr < 4; rr++) {
        sacc[rr] += __shfl_xor_sync(0xffffffffu, sacc[rr], 1);
        sacc[rr] += __shfl_xor_sync(0xffffffffu, sacc[rr], 2);
    }
    float* red = (float*)(SB + OFF_RED);
    if ((lane & 3) == 0) {
#pragma unroll
        for (int rr = 0; rr < 4; rr++) {
            int p = m0 + (lane >> 2) + 8 * rr;
            red[p * 4 + ng] = sacc[rr];
        }
    }
    __syncthreads();

    if (tid < 64) {
        int p = tid;
        float4 r4 = *(const float4*)&red[p * 4];
        float tot = (r4.x + r4.y) + (r4.z + r4.w) + b2[0];
        float sc = 1.0f / (1.0f + expf(-tot));
        int gi = i0 + (p >> 4), gj = j0 + (p & 15);
        hs[gi * BN + gj] = sc;
        hs[gj * BN + gi] = sc;
    }
}

// ---------------- row softmax of adj + 5*log(hs + 1e-8) ----------------
__global__ __launch_bounds__(256)
void softmax_kernel(const float* __restrict__ adj,
                    const float* __restrict__ hs,
                    float* __restrict__ out)
{
    const int row = blockIdx.x;
    const int tid = threadIdx.x;
    __shared__ float red[256];

    float v[4];
    float mx = -3.4e38f;
#pragma unroll
    for (int u = 0; u < 4; u++) {
        int j = tid + 256 * u;
        float s = hs[row * BN + j];
        v[u] = adj[row * BN + j] + 5.0f * logf(s + 1e-8f);
        mx = fmaxf(mx, v[u]);
    }
    red[tid] = mx;
    __syncthreads();
    for (int off = 128; off > 0; off >>= 1) {
        if (tid < off) red[tid] = fmaxf(red[tid], red[tid + off]);
        __syncthreads();
    }
    mx = red[0];
    __syncthreads();

    float sum = 0.0f;
#pragma unroll
    for (int u = 0; u < 4; u++) {
        v[u] = expf(v[u] - mx);
        sum += v[u];
    }
    red[tid] = sum;
    __syncthreads();
    for (int off = 128; off > 0; off >>= 1) {
        if (tid < off) red[tid] += red[tid + off];
        __syncthreads();
    }
    float inv = 1.0f / red[0];
#pragma unroll
    for (int u = 0; u < 4; u++) {
        int j = tid + 256 * u;
        out[row * BN + j] = v[u] * inv;
    }
}

extern "C" void kernel_launch(void* const* d_in, const int* in_sizes, int n_in,
                              void* d_out, int out_size)
{
    const float* X      = (const float*)d_in[0];   // [1024, 512]
    const float* logits = (const float*)d_in[1];   // [1024, 2]
    const float* adj    = (const float*)d_in[2];   // [1024, 1024]
    const float* W1     = (const float*)d_in[3];   // [514, 256]
    const float* b1     = (const float*)d_in[4];   // [256]
    const float* W2     = (const float*)d_in[5];   // [256, 1]
    const float* b2     = (const float*)d_in[6];   // [1]

    float* out = (float*)d_out;          // [adj_refined (1M) | h_scores (1M)]
    float* hs  = out + BN * BN;

    static int configured = 0;
    if (!configured) {
        cudaFuncSetAttribute(scorer_mma, cudaFuncAttributeMaxDynamicSharedMemorySize, SMEM_TOTAL);
        configured = 1;
    }

    prep_kernel<<<FEATN, HN>>>(W1);
    dim3 grid(BN / TJ, BN / TI);   // (64, 256)
    scorer_mma<<<grid, 256, SMEM_TOTAL>>>(X, logits, b1, W1, W2, b2, hs);
    softmax_kernel<<<BN, 256>>>(adj, hs, out);
}